// round 1
// baseline (speedup 1.0000x reference)
#include <cuda_runtime.h>
#include <cuda_bf16.h>

// GuidedFilter: I,p (4,3,1024,1024) fp32, radius 40 box, eps 1e-3.
// 4-kernel separable pipeline:
//   K1: horizontal box sums of {I, p, I*p, I*I}  (per-row block scan)
//   K2: vertical running box sums -> a, b
//   K3: horizontal box sums of {a, b}
//   K4: vertical running box sums of {ha, hb} + final combine with I

#define HH 1024
#define WW 1024
#define NIMG 12
#define RAD 40
#define SEG 128

static __device__ __constant__ float c_eps = 1e-3f;

static constexpr size_t NPIX = (size_t)NIMG * HH * WW;

// scratch (device globals; allocation-free)
__device__ float g_h0[NPIX];
__device__ float g_h1[NPIX];
__device__ float g_h2[NPIX];
__device__ float g_h3[NPIX];
__device__ float g_a[NPIX];
__device__ float g_b[NPIX];

// ---------------------------------------------------------------------------
// K1: per-row horizontal box sums of I, p, I*p, I*I via block prefix scan.
// One block (256 threads) per row. Each thread owns 4 consecutive elements.
// ---------------------------------------------------------------------------
__global__ __launch_bounds__(256) void k_hbox4(const float* __restrict__ I,
                                               const float* __restrict__ P) {
    __shared__ float sI[WW];
    __shared__ float sP[WW];
    __shared__ float pre[WW + 1];
    __shared__ float wtot[8];

    const int tid = threadIdx.x;
    const size_t off = (size_t)blockIdx.x * WW;

    for (int x = tid; x < WW; x += 256) {
        sI[x] = I[off + x];
        sP[x] = P[off + x];
    }
    if (tid == 0) pre[0] = 0.f;
    __syncthreads();

    float* const outs[4] = {g_h0 + off, g_h1 + off, g_h2 + off, g_h3 + off};

    const int lane = tid & 31;
    const int wid  = tid >> 5;
    const int base = tid * 4;

    for (int f = 0; f < 4; ++f) {
        float v[4];
#pragma unroll
        for (int j = 0; j < 4; ++j) {
            int x = base + j;
            float a = sI[x], c = sP[x];
            v[j] = (f == 0) ? a : (f == 1) ? c : (f == 2) ? a * c : a * a;
        }
        // thread-local prefix
        v[1] += v[0]; v[2] += v[1]; v[3] += v[2];
        float tot = v[3];

        // warp inclusive scan of thread totals
        float sc = tot;
#pragma unroll
        for (int o = 1; o < 32; o <<= 1) {
            float n = __shfl_up_sync(0xffffffffu, sc, o);
            if (lane >= o) sc += n;
        }
        if (lane == 31) wtot[wid] = sc;
        __syncthreads();
        if (tid < 32) {
            float wv = (tid < 8) ? wtot[tid] : 0.f;
#pragma unroll
            for (int o = 1; o < 8; o <<= 1) {
                float n = __shfl_up_sync(0xffffffffu, wv, o);
                if (lane >= o) wv += n;
            }
            if (tid < 8) wtot[tid] = wv;
        }
        __syncthreads();

        float offv = (sc - tot) + (wid ? wtot[wid - 1] : 0.f);
#pragma unroll
        for (int j = 0; j < 4; ++j) pre[base + j + 1] = offv + v[j];
        __syncthreads();

        float* o = outs[f];
        for (int x = tid; x < WW; x += 256) {
            int hi = min(x + RAD + 1, WW);
            int lo = max(x - RAD, 0);
            o[x] = pre[hi] - pre[lo];
        }
        __syncthreads();
    }
}

// ---------------------------------------------------------------------------
// K3: per-row horizontal box sums of a, b (same scan, values loaded directly)
// outputs reuse g_h0 / g_h1.
// ---------------------------------------------------------------------------
__global__ __launch_bounds__(256) void k_hbox2() {
    __shared__ float sA[WW];
    __shared__ float sB[WW];
    __shared__ float pre[WW + 1];
    __shared__ float wtot[8];

    const int tid = threadIdx.x;
    const size_t off = (size_t)blockIdx.x * WW;

    for (int x = tid; x < WW; x += 256) {
        sA[x] = g_a[off + x];
        sB[x] = g_b[off + x];
    }
    if (tid == 0) pre[0] = 0.f;
    __syncthreads();

    float* const outs[2] = {g_h0 + off, g_h1 + off};
    const float* const ins[2] = {sA, sB};

    const int lane = tid & 31;
    const int wid  = tid >> 5;
    const int base = tid * 4;

    for (int f = 0; f < 2; ++f) {
        const float* src = ins[f];
        float v[4];
#pragma unroll
        for (int j = 0; j < 4; ++j) v[j] = src[base + j];
        v[1] += v[0]; v[2] += v[1]; v[3] += v[2];
        float tot = v[3];

        float sc = tot;
#pragma unroll
        for (int o = 1; o < 32; o <<= 1) {
            float n = __shfl_up_sync(0xffffffffu, sc, o);
            if (lane >= o) sc += n;
        }
        if (lane == 31) wtot[wid] = sc;
        __syncthreads();
        if (tid < 32) {
            float wv = (tid < 8) ? wtot[tid] : 0.f;
#pragma unroll
            for (int o = 1; o < 8; o <<= 1) {
                float n = __shfl_up_sync(0xffffffffu, wv, o);
                if (lane >= o) wv += n;
            }
            if (tid < 8) wtot[tid] = wv;
        }
        __syncthreads();

        float offv = (sc - tot) + (wid ? wtot[wid - 1] : 0.f);
#pragma unroll
        for (int j = 0; j < 4; ++j) pre[base + j + 1] = offv + v[j];
        __syncthreads();

        float* o = outs[f];
        for (int x = tid; x < WW; x += 256) {
            int hi = min(x + RAD + 1, WW);
            int lo = max(x - RAD, 0);
            o[x] = pre[hi] - pre[lo];
        }
        __syncthreads();
    }
}

// ---------------------------------------------------------------------------
// K2: vertical running box of the 4 horizontal sums; compute a,b per pixel.
// Thread = one column of a 128-row segment. grid = (W/256, H/SEG, NIMG)
// ---------------------------------------------------------------------------
__global__ __launch_bounds__(256) void k_vbox4_ab() {
    const int x   = blockIdx.x * 256 + threadIdx.x;
    const int img = blockIdx.z;
    const int y0  = blockIdx.y * SEG;
    const size_t base = (size_t)img * HH * WW;

    const float* __restrict__ h0 = g_h0 + base;
    const float* __restrict__ h1 = g_h1 + base;
    const float* __restrict__ h2 = g_h2 + base;
    const float* __restrict__ h3 = g_h3 + base;

    float s0 = 0.f, s1 = 0.f, s2 = 0.f, s3 = 0.f;

    const int ys = max(0, y0 - RAD);
    const int ye = min(HH, y0 + RAD);     // exclusive
    for (int yy = ys; yy < ye; ++yy) {
        size_t i = (size_t)yy * WW + x;
        s0 += h0[i]; s1 += h1[i]; s2 += h2[i]; s3 += h3[i];
    }

    const float cntx = (float)(min(x + RAD + 1, WW) - max(x - RAD, 0));

    for (int y = y0; y < y0 + SEG; ++y) {
        int ya = y + RAD;
        if (ya < HH) {
            size_t i = (size_t)ya * WW + x;
            s0 += h0[i]; s1 += h1[i]; s2 += h2[i]; s3 += h3[i];
        }
        float cnty = (float)(min(y + RAD + 1, HH) - max(y - RAD, 0));
        float inv  = 1.0f / (cntx * cnty);
        float mI  = s0 * inv;
        float mP  = s1 * inv;
        float mIp = s2 * inv;
        float mII = s3 * inv;
        float cov = mIp - mI * mP;
        float var = mII - mI * mI;
        float a   = cov / (var + c_eps);
        float b   = mP - a * mI;
        size_t o = base + (size_t)y * WW + x;
        g_a[o] = a;
        g_b[o] = b;
        int yr = y - RAD;
        if (yr >= 0) {
            size_t i = (size_t)yr * WW + x;
            s0 -= h0[i]; s1 -= h1[i]; s2 -= h2[i]; s3 -= h3[i];
        }
    }
}

// ---------------------------------------------------------------------------
// K4: vertical running box of {ha, hb} (in g_h0/g_h1) + combine with I.
// ---------------------------------------------------------------------------
__global__ __launch_bounds__(256) void k_vbox2_final(const float* __restrict__ I,
                                                     float* __restrict__ out) {
    const int x   = blockIdx.x * 256 + threadIdx.x;
    const int img = blockIdx.z;
    const int y0  = blockIdx.y * SEG;
    const size_t base = (size_t)img * HH * WW;

    const float* __restrict__ h0 = g_h0 + base;
    const float* __restrict__ h1 = g_h1 + base;

    float s0 = 0.f, s1 = 0.f;

    const int ys = max(0, y0 - RAD);
    const int ye = min(HH, y0 + RAD);
    for (int yy = ys; yy < ye; ++yy) {
        size_t i = (size_t)yy * WW + x;
        s0 += h0[i]; s1 += h1[i];
    }

    const float cntx = (float)(min(x + RAD + 1, WW) - max(x - RAD, 0));

    for (int y = y0; y < y0 + SEG; ++y) {
        int ya = y + RAD;
        if (ya < HH) {
            size_t i = (size_t)ya * WW + x;
            s0 += h0[i]; s1 += h1[i];
        }
        float cnty = (float)(min(y + RAD + 1, HH) - max(y - RAD, 0));
        float inv  = 1.0f / (cntx * cnty);
        size_t o = base + (size_t)y * WW + x;
        out[o] = (s0 * inv) * I[o] + (s1 * inv);
        int yr = y - RAD;
        if (yr >= 0) {
            size_t i = (size_t)yr * WW + x;
            s0 -= h0[i]; s1 -= h1[i];
        }
    }
}

extern "C" void kernel_launch(void* const* d_in, const int* in_sizes, int n_in,
                              void* d_out, int out_size) {
    const float* I = (const float*)d_in[0];
    const float* P = (const float*)d_in[1];
    float* out = (float*)d_out;

    dim3 rows(NIMG * HH);
    dim3 vgrid(WW / 256, HH / SEG, NIMG);

    k_hbox4<<<rows, 256>>>(I, P);
    k_vbox4_ab<<<vgrid, 256>>>();
    k_hbox2<<<rows, 256>>>();
    k_vbox2_final<<<vgrid, 256>>>(I, out);
}

// round 2
// speedup vs baseline: 2.1467x; 2.1467x over previous
#include <cuda_runtime.h>
#include <cuda_bf16.h>

// GuidedFilter (4,3,1024,1024) fp32, R=40, eps=1e-3.
// Two fused kernels. Box = vertical running sum (registers) then horizontal
// box via block prefix scan in shared (whole 1024-wide row per block).
//   Stage1: I,p -> vbox{I,p,Ip,II} -> hbox -> a,b          (write g_a,g_b)
//   Stage2: a,b -> vbox{a,b} -> hbox -> mean_a*I + mean_b  (write out)

#define HH   1024
#define WW   1024
#define NIMG 12
#define RAD  40
#define SEG  32
#define RS4  (WW / 4)          // row stride in float4 units = 256
#define PIDX(i) ((i) + ((i) >> 5))
#define PSZ  (1024 + 1 + 33)   // padded prefix array size

#define EPS 1e-3f

__device__ float g_a[(size_t)NIMG * HH * WW];
__device__ float g_b[(size_t)NIMG * HH * WW];

static __device__ __forceinline__ float4 f4add(float4 a, float4 b) {
    return make_float4(a.x + b.x, a.y + b.y, a.z + b.z, a.w + b.w);
}
static __device__ __forceinline__ float4 f4sub(float4 a, float4 b) {
    return make_float4(a.x - b.x, a.y - b.y, a.z - b.z, a.w - b.w);
}

// ---------------------------------------------------------------------------
// Stage 1
// ---------------------------------------------------------------------------
__global__ __launch_bounds__(256) void k_stage1(const float* __restrict__ I,
                                                const float* __restrict__ P) {
    __shared__ float pre0[PSZ], pre1[PSZ], pre2[PSZ], pre3[PSZ];
    __shared__ float4 wt[8];

    const int tid  = threadIdx.x;
    const int lane = tid & 31;
    const int wid  = tid >> 5;
    const int c0   = tid * 4;
    const int img  = blockIdx.y;
    const int y0   = blockIdx.x * SEG;
    const size_t b4 = (size_t)img * HH * RS4;     // image base in float4 units

    const float4* __restrict__ I4 = (const float4*)I + b4;
    const float4* __restrict__ P4 = (const float4*)P + b4;
    float4* __restrict__ A4 = (float4*)g_a + b4;
    float4* __restrict__ B4 = (float4*)g_b + b4;

    // vertical running sums (4 fields x 4 cols)
    float4 vI = make_float4(0, 0, 0, 0);
    float4 vP = vI, vIp = vI, vII = vI;

    const int ys = max(0, y0 - RAD);
    const int ye = min(HH, y0 + RAD);   // exclusive
#pragma unroll 2
    for (int yy = ys; yy < ye; ++yy) {
        float4 i4 = I4[(size_t)yy * RS4 + tid];
        float4 p4 = P4[(size_t)yy * RS4 + tid];
        vI  = f4add(vI, i4);
        vP  = f4add(vP, p4);
        vIp = f4add(vIp, make_float4(i4.x * p4.x, i4.y * p4.y, i4.z * p4.z, i4.w * p4.w));
        vII = f4add(vII, make_float4(i4.x * i4.x, i4.y * i4.y, i4.z * i4.z, i4.w * i4.w));
    }

    int hiI[4], loI[4];
    float cntx[4];
#pragma unroll
    for (int j = 0; j < 4; ++j) {
        int c  = c0 + j;
        int hi = min(c + RAD + 1, WW);
        int lo = max(c - RAD, 0);
        hiI[j] = PIDX(hi);
        loI[j] = PIDX(lo);
        cntx[j] = (float)(hi - lo);
    }
    if (tid == 0) {
        pre0[PIDX(0)] = 0.f; pre1[PIDX(0)] = 0.f;
        pre2[PIDX(0)] = 0.f; pre3[PIDX(0)] = 0.f;
    }

    for (int y = y0; y < y0 + SEG; ++y) {
        int ya = y + RAD;
        if (ya < HH) {
            float4 i4 = I4[(size_t)ya * RS4 + tid];
            float4 p4 = P4[(size_t)ya * RS4 + tid];
            vI  = f4add(vI, i4);
            vP  = f4add(vP, p4);
            vIp = f4add(vIp, make_float4(i4.x * p4.x, i4.y * p4.y, i4.z * p4.z, i4.w * p4.w));
            vII = f4add(vII, make_float4(i4.x * i4.x, i4.y * i4.y, i4.z * i4.z, i4.w * i4.w));
        }

        // transpose to per-column payloads (field0..3) and scan
        float4 q[4];
        q[0] = make_float4(vI.x, vP.x, vIp.x, vII.x);
        q[1] = make_float4(vI.y, vP.y, vIp.y, vII.y);
        q[2] = make_float4(vI.z, vP.z, vIp.z, vII.z);
        q[3] = make_float4(vI.w, vP.w, vIp.w, vII.w);
        q[1] = f4add(q[1], q[0]);
        q[2] = f4add(q[2], q[1]);
        q[3] = f4add(q[3], q[2]);
        float4 tot = q[3];
        float4 sc  = tot;
#pragma unroll
        for (int o = 1; o < 32; o <<= 1) {
            float ax = __shfl_up_sync(0xffffffffu, sc.x, o);
            float ay = __shfl_up_sync(0xffffffffu, sc.y, o);
            float az = __shfl_up_sync(0xffffffffu, sc.z, o);
            float aw = __shfl_up_sync(0xffffffffu, sc.w, o);
            if (lane >= o) { sc.x += ax; sc.y += ay; sc.z += az; sc.w += aw; }
        }
        if (lane == 31) wt[wid] = sc;
        __syncthreads();
        if (tid < 32) {
            float4 w = (lane < 8) ? wt[lane] : make_float4(0, 0, 0, 0);
#pragma unroll
            for (int o = 1; o < 8; o <<= 1) {
                float ax = __shfl_up_sync(0xffffffffu, w.x, o);
                float ay = __shfl_up_sync(0xffffffffu, w.y, o);
                float az = __shfl_up_sync(0xffffffffu, w.z, o);
                float aw = __shfl_up_sync(0xffffffffu, w.w, o);
                if (lane >= o) { w.x += ax; w.y += ay; w.z += az; w.w += aw; }
            }
            if (lane < 8) wt[lane] = w;
        }
        __syncthreads();
        float4 off = f4sub(sc, tot);
        if (wid) off = f4add(off, wt[wid - 1]);
#pragma unroll
        for (int j = 0; j < 4; ++j) {
            float4 t = f4add(off, q[j]);
            int ip = PIDX(c0 + j + 1);
            pre0[ip] = t.x; pre1[ip] = t.y; pre2[ip] = t.z; pre3[ip] = t.w;
        }
        __syncthreads();

        float cnty = (float)(min(y + RAD + 1, HH) - max(y - RAD, 0));
        float4 av, bv;
        float* ap = &av.x;
        float* bp = &bv.x;
#pragma unroll
        for (int j = 0; j < 4; ++j) {
            float s0 = pre0[hiI[j]] - pre0[loI[j]];
            float s1 = pre1[hiI[j]] - pre1[loI[j]];
            float s2 = pre2[hiI[j]] - pre2[loI[j]];
            float s3 = pre3[hiI[j]] - pre3[loI[j]];
            float inv = 1.0f / (cntx[j] * cnty);
            float mI  = s0 * inv;
            float mP  = s1 * inv;
            float mIp = s2 * inv;
            float mII = s3 * inv;
            float a = (mIp - mI * mP) / ((mII - mI * mI) + EPS);
            ap[j] = a;
            bp[j] = mP - a * mI;
        }
        A4[(size_t)y * RS4 + tid] = av;
        B4[(size_t)y * RS4 + tid] = bv;

        int yr = y - RAD;
        if (yr >= 0) {
            float4 i4 = I4[(size_t)yr * RS4 + tid];
            float4 p4 = P4[(size_t)yr * RS4 + tid];
            vI  = f4sub(vI, i4);
            vP  = f4sub(vP, p4);
            vIp = f4sub(vIp, make_float4(i4.x * p4.x, i4.y * p4.y, i4.z * p4.z, i4.w * p4.w));
            vII = f4sub(vII, make_float4(i4.x * i4.x, i4.y * i4.y, i4.z * i4.z, i4.w * i4.w));
        }
    }
}

// ---------------------------------------------------------------------------
// Stage 2
// ---------------------------------------------------------------------------
__global__ __launch_bounds__(256) void k_stage2(const float* __restrict__ I,
                                                float* __restrict__ out) {
    __shared__ float pre0[PSZ], pre1[PSZ];
    __shared__ float2 wt[8];

    const int tid  = threadIdx.x;
    const int lane = tid & 31;
    const int wid  = tid >> 5;
    const int c0   = tid * 4;
    const int img  = blockIdx.y;
    const int y0   = blockIdx.x * SEG;
    const size_t b4 = (size_t)img * HH * RS4;

    const float4* __restrict__ A4 = (const float4*)g_a + b4;
    const float4* __restrict__ B4 = (const float4*)g_b + b4;
    const float4* __restrict__ I4 = (const float4*)I + b4;
    float4* __restrict__ O4 = (float4*)out + b4;

    float4 vA = make_float4(0, 0, 0, 0);
    float4 vB = vA;

    const int ys = max(0, y0 - RAD);
    const int ye = min(HH, y0 + RAD);
#pragma unroll 2
    for (int yy = ys; yy < ye; ++yy) {
        vA = f4add(vA, A4[(size_t)yy * RS4 + tid]);
        vB = f4add(vB, B4[(size_t)yy * RS4 + tid]);
    }

    int hiI[4], loI[4];
    float cntx[4];
#pragma unroll
    for (int j = 0; j < 4; ++j) {
        int c  = c0 + j;
        int hi = min(c + RAD + 1, WW);
        int lo = max(c - RAD, 0);
        hiI[j] = PIDX(hi);
        loI[j] = PIDX(lo);
        cntx[j] = (float)(hi - lo);
    }
    if (tid == 0) { pre0[PIDX(0)] = 0.f; pre1[PIDX(0)] = 0.f; }

    for (int y = y0; y < y0 + SEG; ++y) {
        int ya = y + RAD;
        if (ya < HH) {
            vA = f4add(vA, A4[(size_t)ya * RS4 + tid]);
            vB = f4add(vB, B4[(size_t)ya * RS4 + tid]);
        }

        float2 q[4];
        q[0] = make_float2(vA.x, vB.x);
        q[1] = make_float2(vA.y + q[0].x * 0.f + vA.y * 0.f, vB.y); // placeholder removed below
        q[1] = make_float2(vA.y, vB.y);
        q[2] = make_float2(vA.z, vB.z);
        q[3] = make_float2(vA.w, vB.w);
        q[1].x += q[0].x; q[1].y += q[0].y;
        q[2].x += q[1].x; q[2].y += q[1].y;
        q[3].x += q[2].x; q[3].y += q[2].y;
        float2 tot = q[3];
        float2 sc  = tot;
#pragma unroll
        for (int o = 1; o < 32; o <<= 1) {
            float ax = __shfl_up_sync(0xffffffffu, sc.x, o);
            float ay = __shfl_up_sync(0xffffffffu, sc.y, o);
            if (lane >= o) { sc.x += ax; sc.y += ay; }
        }
        if (lane == 31) wt[wid] = sc;
        __syncthreads();
        if (tid < 32) {
            float2 w = (lane < 8) ? wt[lane] : make_float2(0, 0);
#pragma unroll
            for (int o = 1; o < 8; o <<= 1) {
                float ax = __shfl_up_sync(0xffffffffu, w.x, o);
                float ay = __shfl_up_sync(0xffffffffu, w.y, o);
                if (lane >= o) { w.x += ax; w.y += ay; }
            }
            if (lane < 8) wt[lane] = w;
        }
        __syncthreads();
        float2 off = make_float2(sc.x - tot.x, sc.y - tot.y);
        if (wid) { off.x += wt[wid - 1].x; off.y += wt[wid - 1].y; }
#pragma unroll
        for (int j = 0; j < 4; ++j) {
            int ip = PIDX(c0 + j + 1);
            pre0[ip] = off.x + q[j].x;
            pre1[ip] = off.y + q[j].y;
        }
        __syncthreads();

        float cnty = (float)(min(y + RAD + 1, HH) - max(y - RAD, 0));
        float4 i4 = I4[(size_t)y * RS4 + tid];
        float4 ov;
        float* op = &ov.x;
        const float* ip4 = &i4.x;
#pragma unroll
        for (int j = 0; j < 4; ++j) {
            float sa = pre0[hiI[j]] - pre0[loI[j]];
            float sb = pre1[hiI[j]] - pre1[loI[j]];
            float inv = 1.0f / (cntx[j] * cnty);
            op[j] = (sa * inv) * ip4[j] + (sb * inv);
        }
        O4[(size_t)y * RS4 + tid] = ov;

        int yr = y - RAD;
        if (yr >= 0) {
            vA = f4sub(vA, A4[(size_t)yr * RS4 + tid]);
            vB = f4sub(vB, B4[(size_t)yr * RS4 + tid]);
        }
    }
}

extern "C" void kernel_launch(void* const* d_in, const int* in_sizes, int n_in,
                              void* d_out, int out_size) {
    const float* I = (const float*)d_in[0];
    const float* P = (const float*)d_in[1];
    float* out = (float*)d_out;

    dim3 g(HH / SEG, NIMG);
    k_stage1<<<g, 256>>>(I, P);
    k_stage2<<<g, 256>>>(I, out);
}